// round 6
// baseline (speedup 1.0000x reference)
#include <cuda_runtime.h>
#include <math.h>
#include <stdint.h>

// Problem constants
#define CDIM    64
#define NE      2048
#define HW      4096
#define NPIX    65536            // 16 * 4096
#define NELEM   4194304          // NPIX * CDIM

// Output layout: z_q [NELEM], loss, perplexity, indices [NPIX]
#define OFF_LOSS  NELEM
#define OFF_PERP  (NELEM + 1)
#define OFF_IDX   (NELEM + 2)

// Argmax tiling: 64 px per block x full codebook, chunks of 64 codes
#define BP      64
#define CHUNK   64
#define NCH     32
#define THREADS 256
#define GRID_ARG (NPIX / BP)     // 1024

#define ZS_FLOATS (BP * CDIM)        // 4096 floats = 16 KB, [px][k] swizzled
#define EB_FLOATS (CHUNK * CDIM)     // 4096 floats = 16 KB per buffer, [code][k]
#define SMEM_BYTES ((ZS_FLOATS + 2 * EB_FLOATS) * 4)   // 48 KB

#define OUTBLOCKS 4096

__device__ int   g_idx[NPIX];
__device__ int   g_counts[NE];
__device__ float g_partials[OUTBLOCKS];

// ---------------------------------------------------------------------------
// Kernel 1: fused GEMM-argmax, broadcast-optimized.
// Warp: pgrp = lane&7 (px), cgrp = lane>>3 (codes).  Block: 8 warps =
// 2 (px halves) x 4 (code quarters).  Thread: 4 px x 4 codes.
//   px[j]   = 32*wpx  + 8*j + pgrp      (j = 0..3)
//   code[n] = 16*wc   + 4*n + cgrp      (n = 0..3)
// zs [px][k]: 16B group for kgrp c at g = c ^ (px&15)  -> z LDS.128 has 8
//   unique rows (128B, conflict-free) broadcast to 4 cgrps = 1 wavefront.
// es [code][k]: group g = c ^ (code&15) -> e LDS.128 has 4 unique rows
//   (64B) broadcast to 8 pgrps = 1 wavefront.
// Per k-quad: 8 LDS.128 (8 wavefronts) + 32 fma.f32x2 (16 pipe-cycles).
// ---------------------------------------------------------------------------
__global__ void __launch_bounds__(THREADS, 2)
vq_argmax(const float* __restrict__ z, const float* __restrict__ cb,
          float* __restrict__ out, int out_size) {
    extern __shared__ float smem[];
    float* zs = smem;                  // [64][64] swizzled
    float* es = smem + ZS_FLOATS;      // 2 x [64][64] swizzled

    const int tid  = threadIdx.x;
    const int lane = tid & 31;
    const int wid  = tid >> 5;
    const int pgrp = lane & 7;
    const int cgrp = lane >> 3;        // 0..3
    const int wpx  = wid & 1;          // px half
    const int wc   = wid >> 1;         // code quarter

    if (blockIdx.x == 0) {             // zero histogram for vq_out
#pragma unroll
        for (int i = 0; i < NE / THREADS; ++i)
            g_counts[i * THREADS + tid] = 0;
    }

    const int pixBase = blockIdx.x * BP;
    const int b       = pixBase >> 12;
    const int hwBase  = pixBase & 4095;
    const float* zimg = z + (size_t)b * CDIM * HW + hwBase;

    const unsigned esu = (unsigned)__cvta_generic_to_shared(es);

    // ---- cp.async prefetch chunks 0 and 1 (4 x 16B per thread per chunk) ----
#pragma unroll
    for (int pc = 0; pc < 2; ++pc) {
        const float* src = cb + (size_t)pc * CHUNK * CDIM;
        const unsigned dstb = esu + pc * EB_FLOATS * 4;
#pragma unroll
        for (int i = 0; i < 4; ++i) {
            int idx  = i * THREADS + tid;
            int code = idx >> 4, c = idx & 15;
            unsigned dst = dstb + (unsigned)(code * 256 + ((c ^ (code & 15)) << 4));
            asm volatile("cp.async.cg.shared.global [%0], [%1], 16;"
                         :: "r"(dst), "l"(src + code * CDIM + c * 4));
        }
        asm volatile("cp.async.commit_group;");
    }

    // ---- zs fill: transpose z[k][px] -> zs[px][k] with group swizzle ----
#pragma unroll
    for (int i = 0; i < 4; ++i) {
        int idx = i * THREADS + tid;        // 1024 float4 items
        int cd = idx >> 4, p4 = idx & 15;
        float4 v = ((const float4*)(zimg + (size_t)cd * HW))[p4];
        float vv[4] = { v.x, v.y, v.z, v.w };
#pragma unroll
        for (int r = 0; r < 4; ++r) {
            int px = p4 * 4 + r;
            zs[px * CDIM + 4 * ((cd >> 2) ^ (px & 15)) + (cd & 3)] = vv[r];
        }
    }

    // ---- precompute XOR-swizzle base addresses ----
    uintptr_t zb[4], eb[4];
#pragma unroll
    for (int j = 0; j < 4; ++j) {
        int px = 32 * wpx + 8 * j + pgrp;
        zb[j] = (uintptr_t)zs + px * 256 + ((px & 15) << 4);
    }
#pragma unroll
    for (int n = 0; n < 4; ++n) {
        int cl = 16 * wc + 4 * n + cgrp;   // code row within chunk
        eb[n] = (uintptr_t)es + cl * 256 + ((cl & 15) << 4);
    }

    float mx[4];
    int   mi[4];
#pragma unroll
    for (int j = 0; j < 4; ++j) { mx[j] = -3.402823e38f; mi[j] = 0; }

    for (int ch = 0; ch < NCH; ++ch) {
        if (ch == NCH - 1) asm volatile("cp.async.wait_group 0;");
        else               asm volatile("cp.async.wait_group 1;");
        __syncthreads();

        const uintptr_t ebOff = (uintptr_t)((ch & 1) * (EB_FLOATS * 4));

        unsigned long long acc[4][4];
#pragma unroll
        for (int j = 0; j < 4; ++j)
#pragma unroll
            for (int n = 0; n < 4; ++n) acc[j][n] = 0ull;

#pragma unroll
        for (int c = 0; c < 16; ++c) {      // k-quad: dims 4c..4c+3
            ulonglong2 zv[4], ev[4];
#pragma unroll
            for (int j = 0; j < 4; ++j)
                zv[j] = *(const ulonglong2*)(zb[j] ^ (uintptr_t)(c << 4));
#pragma unroll
            for (int n = 0; n < 4; ++n)
                ev[n] = *(const ulonglong2*)((eb[n] + ebOff) ^ (uintptr_t)(c << 4));
#pragma unroll
            for (int j = 0; j < 4; ++j)
#pragma unroll
                for (int n = 0; n < 4; ++n)
                    asm("fma.rn.f32x2 %0, %1, %2, %0;"
                        : "+l"(acc[j][n]) : "l"(zv[j].x), "l"(ev[n].x));
#pragma unroll
            for (int j = 0; j < 4; ++j)
#pragma unroll
                for (int n = 0; n < 4; ++n)
                    asm("fma.rn.f32x2 %0, %1, %2, %0;"
                        : "+l"(acc[j][n]) : "l"(zv[j].y), "l"(ev[n].y));
        }

        __syncthreads();                    // all warps done reading buffer
        if (ch + 2 < NCH) {                 // refill this buffer
            const float* src = cb + (size_t)(ch + 2) * CHUNK * CDIM;
            const unsigned dstb = esu + (ch & 1) * EB_FLOATS * 4;
#pragma unroll
            for (int i = 0; i < 4; ++i) {
                int idx  = i * THREADS + tid;
                int code = idx >> 4, c = idx & 15;
                unsigned dst = dstb + (unsigned)(code * 256 + ((c ^ (code & 15)) << 4));
                asm volatile("cp.async.cg.shared.global [%0], [%1], 16;"
                             :: "r"(dst), "l"(src + code * CDIM + c * 4));
            }
            asm volatile("cp.async.commit_group;");
        }

        // fold chunk winners (ascending code order, strict > -> lowest index)
        const int cBase = ch * CHUNK + 16 * wc + cgrp;
#pragma unroll
        for (int j = 0; j < 4; ++j) {
#pragma unroll
            for (int n = 0; n < 4; ++n) {
                unsigned lo, hi;
                asm("mov.b64 {%0, %1}, %2;" : "=r"(lo), "=r"(hi) : "l"(acc[j][n]));
                float s = __uint_as_float(lo) + __uint_as_float(hi);
                if (s > mx[j]) { mx[j] = s; mi[j] = cBase + 4 * n; }
            }
        }
    }

    // ---- reduce over the 4 cgrp lanes (xor 8, 16) ----
#pragma unroll
    for (int off = 8; off <= 16; off <<= 1) {
#pragma unroll
        for (int j = 0; j < 4; ++j) {
            float om = __shfl_xor_sync(0xFFFFFFFFu, mx[j], off);
            int   oi = __shfl_xor_sync(0xFFFFFFFFu, mi[j], off);
            if (om > mx[j] || (om == mx[j] && oi < mi[j])) { mx[j] = om; mi[j] = oi; }
        }
    }

    // ---- cross-warp reduce via smem (reuse zs region; mainloop done) ----
    float* red_mx = smem;                   // [4][64]
    int*   red_mi = (int*)(smem + 256);     // [4][64]
    if (cgrp == 0) {
#pragma unroll
        for (int j = 0; j < 4; ++j) {
            int p = 32 * wpx + 8 * j + pgrp;
            red_mx[wc * 64 + p] = mx[j];
            red_mi[wc * 64 + p] = mi[j];
        }
    }
    __syncthreads();

    if (tid < 64) {
        float bm = red_mx[tid];
        int   bi = red_mi[tid];
#pragma unroll
        for (int w = 1; w < 4; ++w) {
            float om = red_mx[w * 64 + tid];
            int   oi = red_mi[w * 64 + tid];
            if (om > bm || (om == bm && oi < bi)) { bm = om; bi = oi; }
        }
        const int p = pixBase + tid;
        g_idx[p] = bi;
        int o = OFF_IDX + p;
        if (o < out_size) out[o] = (float)bi;
    }
}

// ---------------------------------------------------------------------------
// Kernel 2: z_q gather + straight-through output + MSE partials + histogram.
// ---------------------------------------------------------------------------
__global__ void __launch_bounds__(256)
vq_out(const float* __restrict__ z, const float* __restrict__ cb,
       float* __restrict__ out) {
    const int t = blockIdx.x * 256 + threadIdx.x;   // float4 index
    const int e = t * 4;
    const int c  = (e >> 12) & 63;
    const int b  = e >> 18;
    const int hw = e & 4095;
    const int p  = (b << 12) + hw;

    const float4 zv = *(const float4*)(z + e);
    const int4  iv  = *(const int4*)(g_idx + p);

    const float q0 = cb[iv.x * CDIM + c];
    const float q1 = cb[iv.y * CDIM + c];
    const float q2 = cb[iv.z * CDIM + c];
    const float q3 = cb[iv.w * CDIM + c];

    float4 ov;
    ov.x = zv.x + (q0 - zv.x);
    ov.y = zv.y + (q1 - zv.y);
    ov.z = zv.z + (q2 - zv.z);
    ov.w = zv.w + (q3 - zv.w);
    *(float4*)(out + e) = ov;

    if (c == 0) {
        atomicAdd(&g_counts[iv.x], 1);
        atomicAdd(&g_counts[iv.y], 1);
        atomicAdd(&g_counts[iv.z], 1);
        atomicAdd(&g_counts[iv.w], 1);
    }

    const float d0 = q0 - zv.x, d1 = q1 - zv.y, d2 = q2 - zv.z, d3 = q3 - zv.w;
    float s = d0 * d0 + d1 * d1 + d2 * d2 + d3 * d3;

    __shared__ float red[256];
    red[threadIdx.x] = s;
    __syncthreads();
#pragma unroll
    for (int off = 128; off; off >>= 1) {
        if (threadIdx.x < off) red[threadIdx.x] += red[threadIdx.x + off];
        __syncthreads();
    }
    if (threadIdx.x == 0) g_partials[blockIdx.x] = red[0];
}

// ---------------------------------------------------------------------------
// Kernel 3: deterministic finalize — loss and perplexity (1024 threads).
// ---------------------------------------------------------------------------
__global__ void vq_fin(float* __restrict__ out, int out_size) {
    __shared__ float red[1024];
    const int t = threadIdx.x;

    float s = 0.0f;
#pragma unroll
    for (int i = 0; i < OUTBLOCKS / 1024; ++i) s += g_partials[i * 1024 + t];
    red[t] = s;
    __syncthreads();
#pragma unroll
    for (int off = 512; off; off >>= 1) {
        if (t < off) red[t] += red[t + off];
        __syncthreads();
    }
    if (t == 0 && OFF_LOSS < out_size)
        out[OFF_LOSS] = 1.25f * red[0] * (1.0f / (float)NELEM);
    __syncthreads();

    float h = 0.0f;
#pragma unroll
    for (int i = 0; i < NE / 1024; ++i) {
        float em = (float)g_counts[i * 1024 + t] * (1.0f / (float)NPIX);
        h += em * logf(em + 1e-10f);
    }
    red[t] = h;
    __syncthreads();
#pragma unroll
    for (int off = 512; off; off >>= 1) {
        if (t < off) red[t] += red[t + off];
        __syncthreads();
    }
    if (t == 0 && OFF_PERP < out_size)
        out[OFF_PERP] = expf(-red[0]);
}

// ---------------------------------------------------------------------------
extern "C" void kernel_launch(void* const* d_in, const int* in_sizes, int n_in,
                              void* d_out, int out_size) {
    const float* z  = (const float*)d_in[0];
    const float* cb = (const float*)d_in[1];
    float* out = (float*)d_out;

    cudaFuncSetAttribute(vq_argmax, cudaFuncAttributeMaxDynamicSharedMemorySize,
                         SMEM_BYTES);

    vq_argmax<<<GRID_ARG, THREADS, SMEM_BYTES>>>(z, cb, out, out_size);
    vq_out<<<OUTBLOCKS, 256>>>(z, cb, out);
    vq_fin<<<1, 1024>>>(out, out_size);
}

// round 11
// speedup vs baseline: 2.9376x; 2.9376x over previous
#include <cuda_runtime.h>
#include <cuda_bf16.h>
#include <math.h>
#include <stdint.h>

// Problem constants
#define CDIM    64
#define NE      2048
#define HW      4096
#define NPIX    65536            // 16 * 4096
#define NELEM   4194304          // NPIX * CDIM

// Output layout: z_q [NELEM], loss, perplexity, indices [NPIX]
#define OFF_LOSS  NELEM
#define OFF_PERP  (NELEM + 1)
#define OFF_IDX   (NELEM + 2)

#define OUTBLOCKS 4096

// MMA tiling: block = 8 warps x 16 px = 128 px; codes in chunks of 128 (16 n-tiles)
#define BPX       128
#define GRID_MMA  (NPIX / BPX)        // 512  (single wave at occ 4)
#define NT_TOTAL  (NE / 8)            // 256 n-tiles of 8 codes
#define CHUNK_NT  16                  // n-tiles per smem chunk (128 codes = 16KB frag)
#define NCHUNK    (NT_TOTAL / CHUNK_NT)  // 16
#define CAND_CAP  4096
#define CAPG      (1 << 20)

// err bound coefficient: thr = amax - COEF * ||z_p|| * Emax,  COEF = 2*gamma = 2^-5
#define COEF_2G   0.03125f

// device state
__device__ uint2 g_cbf[NT_TOTAL * 4 * 32];       // fragment-ready bf16 codebook (256KB)
__device__ __nv_bfloat16 g_zh[NELEM];            // z bf16, [px][k] (8MB)
__device__ float g_zt[NELEM];                    // z fp32, [px][k] (16MB, for exact rescore)
__device__ float g_zn[NPIX];                     // ||z_p||
__device__ unsigned long long g_key[NPIX];       // exact (value,idx) max keys
__device__ int   g_cand[CAPG];                   // candidate list: (px<<11)|code
__device__ int   g_ncand;
__device__ int   g_emax_bits;                    // max ||e_c||^2 as float bits
__device__ int   g_counts[NE];
__device__ float g_partials[OUTBLOCKS];

// ---------------------------------------------------------------------------
// Kernel 1: prep z — transpose to [px][k], write fp32 copy + bf16 + norms.
// Also zero per-replay state (keys, counters).
// ---------------------------------------------------------------------------
__global__ void __launch_bounds__(256)
vq_prep_z(const float* __restrict__ z) {
    __shared__ float ts[64 * 65];
    __shared__ float sn[256];
    const int tid = threadIdx.x;
    const int b   = blockIdx.x >> 6;
    const int hwt = blockIdx.x & 63;

    if (blockIdx.x == 0) {
#pragma unroll
        for (int i = 0; i < NE / 256; ++i) g_counts[i * 256 + tid] = 0;
        if (tid == 0) { g_ncand = 0; g_emax_bits = 0; }
    }
    if (tid < 64) g_key[blockIdx.x * 64 + tid] = 0ull;

    const float* src = z + (size_t)b * CDIM * HW + hwt * 64;
#pragma unroll
    for (int i = 0; i < 16; ++i) {
        int idx = i * 256 + tid;
        int c = idx >> 6, p = idx & 63;
        ts[c * 65 + p] = src[(size_t)c * HW + p];
    }
    __syncthreads();

    const int pl = tid >> 2, q = tid & 3;       // pixel-local, c-quarter
    const int px = blockIdx.x * 64 + pl;
    float v[16];
    float nrm = 0.f;
#pragma unroll
    for (int cc = 0; cc < 16; ++cc) {
        float x = ts[(q * 16 + cc) * 65 + pl];
        v[cc] = x; nrm += x * x;
    }
    float4* zt4 = (float4*)(g_zt + (size_t)px * 64 + q * 16);
    zt4[0] = make_float4(v[0], v[1], v[2], v[3]);
    zt4[1] = make_float4(v[4], v[5], v[6], v[7]);
    zt4[2] = make_float4(v[8], v[9], v[10], v[11]);
    zt4[3] = make_float4(v[12], v[13], v[14], v[15]);

    unsigned hw_[8];
#pragma unroll
    for (int wdx = 0; wdx < 8; ++wdx) {
        __nv_bfloat162 h2 = __floats2bfloat162_rn(v[2 * wdx], v[2 * wdx + 1]);
        hw_[wdx] = *(unsigned*)&h2;
    }
    uint4* zh4 = (uint4*)((unsigned*)g_zh + (size_t)px * 32 + q * 8);
    zh4[0] = make_uint4(hw_[0], hw_[1], hw_[2], hw_[3]);
    zh4[1] = make_uint4(hw_[4], hw_[5], hw_[6], hw_[7]);

    sn[tid] = nrm;
    __syncthreads();
    if (tid < 64)
        g_zn[blockIdx.x * 64 + tid] =
            sqrtf(sn[tid * 4] + sn[tid * 4 + 1] + sn[tid * 4 + 2] + sn[tid * 4 + 3]);
}

// ---------------------------------------------------------------------------
// Kernel 2: prep codebook into fragment-ready bf16 layout.
// Entry (nt, kc, lane): 8B = {word(kc*8+j) , word(kc*8+j+4)} of code nt*8+(lane>>2),
// word w = bf16 pair (k=2w, 2w+1).  Matches mma.m16n8k16 b-frag exactly.
// ---------------------------------------------------------------------------
__global__ void __launch_bounds__(256)
vq_prep_cb(const float* __restrict__ cb) {
    int id = blockIdx.x * 256 + threadIdx.x;        // 128 blocks -> 32768
    int lane = id & 31, kc = (id >> 5) & 3, nt = id >> 7;
    int code = nt * 8 + (lane >> 2), j = lane & 3;
    int w1 = kc * 8 + j, w2 = w1 + 4;
    const float* r = cb + (size_t)code * CDIM;
    __nv_bfloat162 b0 = __floats2bfloat162_rn(r[2 * w1], r[2 * w1 + 1]);
    __nv_bfloat162 b1 = __floats2bfloat162_rn(r[2 * w2], r[2 * w2 + 1]);
    g_cbf[id] = make_uint2(*(unsigned*)&b0, *(unsigned*)&b1);
}

// ---------------------------------------------------------------------------
// Kernel 3: per-code norms -> Emax (float-bits atomicMax; norms >= 0).
// ---------------------------------------------------------------------------
__global__ void vq_cbnorm(const float* __restrict__ cb) {
    int code = blockIdx.x * 256 + threadIdx.x;      // 8 blocks
    const float4* r = (const float4*)(cb + (size_t)code * CDIM);
    float s = 0.f;
#pragma unroll
    for (int i = 0; i < 16; ++i) {
        float4 v = r[i];
        s += v.x * v.x + v.y * v.y + v.z * v.z + v.w * v.w;
    }
    atomicMax(&g_emax_bits, __float_as_int(s));
}

// ---------------------------------------------------------------------------
// Kernel 4: bf16 HMMA GEMM, two sweeps.
// Sweep 1 (it 0..15): per-pixel approx max.  Sweep 2 (it 16..31): identical
// MMAs, emit candidates approx >= amax - COEF*||z||*Emax to smem list.
// ---------------------------------------------------------------------------
__global__ void __launch_bounds__(256, 4)
vq_mma(float* __restrict__ out, int out_size) {
    extern __shared__ char smem[];
    uint2* s_cb   = (uint2*)smem;                       // [2][2048] (32KB)
    float* s_zn   = (float*)(smem + 32768);             // [128]
    float* s_thr  = (float*)(smem + 32768 + 512);       // [128]
    int*   s_cand = (int*)(smem + 32768 + 1024);        // [4096]
    int*   s_nc   = (int*)(smem + 32768 + 1024 + CAND_CAP * 4);
    int*   s_base = s_nc + 1;

    const int tid  = threadIdx.x;
    const int lane = tid & 31;
    const int w    = tid >> 5;
    const int g    = lane >> 2;       // row-in-16 / n-col
    const int i4   = lane & 3;        // k-pair / col-pair index
    const int px0  = blockIdx.x * BPX;
    const int pxw  = px0 + w * 16;

    unsigned smem_u;
    asm("{ .reg .u64 t; cvta.to.shared.u64 t, %1; cvt.u32.u64 %0, t; }"
        : "=r"(smem_u) : "l"(smem));

    if (tid == 0) *s_nc = 0;
    if (tid < 128) s_zn[tid] = g_zn[px0 + tid];

    // A fragments (whole k range, resident in regs): 4 k-chunks x 4 b32
    unsigned a[4][4];
    {
        const unsigned* zw = (const unsigned*)g_zh;
        const size_t rA = (size_t)(pxw + g) * 32;
        const size_t rB = (size_t)(pxw + g + 8) * 32;
#pragma unroll
        for (int kc = 0; kc < 4; ++kc) {
            a[kc][0] = zw[rA + kc * 8 + i4];
            a[kc][1] = zw[rB + kc * 8 + i4];
            a[kc][2] = zw[rA + kc * 8 + i4 + 4];
            a[kc][3] = zw[rB + kc * 8 + i4 + 4];
        }
    }

    const float coef = COEF_2G * sqrtf(__int_as_float(g_emax_bits));

    // prefetch chunks 0,1 (16KB each: 4 x 16B per thread)
#pragma unroll
    for (int pc = 0; pc < 2; ++pc) {
#pragma unroll
        for (int ii = 0; ii < 4; ++ii) {
            int o = (ii * 256 + tid) * 16;
            asm volatile("cp.async.cg.shared.global [%0], [%1], 16;"
                :: "r"(smem_u + pc * 16384 + o),
                   "l"((const char*)g_cbf + pc * 16384 + o));
        }
        asm volatile("cp.async.commit_group;");
    }

    float mxA = -3.402823e38f, mxB = -3.402823e38f;
    float thrA = 0.f, thrB = 0.f;

    for (int it = 0; it < 32; ++it) {
        const int ch = it & 15;
        if (it == 31) asm volatile("cp.async.wait_group 0;");
        else          asm volatile("cp.async.wait_group 1;");
        __syncthreads();

        if (it == 16) {
            // close sweep 1: row maxima across the 4 col-lanes, compute thresholds
#pragma unroll
            for (int off = 1; off <= 2; off <<= 1) {
                mxA = fmaxf(mxA, __shfl_xor_sync(0xFFFFFFFFu, mxA, off));
                mxB = fmaxf(mxB, __shfl_xor_sync(0xFFFFFFFFu, mxB, off));
            }
            if (i4 == 0) {
                s_thr[w * 16 + g]     = mxA - coef * s_zn[w * 16 + g];
                s_thr[w * 16 + g + 8] = mxB - coef * s_zn[w * 16 + g + 8];
            }
            __syncthreads();
            thrA = s_thr[w * 16 + g];
            thrB = s_thr[w * 16 + g + 8];
        }

        const uint2* cbb = s_cb + (it & 1) * 2048;
#pragma unroll 4
        for (int ntl = 0; ntl < CHUNK_NT; ++ntl) {
            uint2 b[4];
#pragma unroll
            for (int kc = 0; kc < 4; ++kc)
                b[kc] = cbb[ntl * 128 + kc * 32 + lane];

            float c0 = 0.f, c1 = 0.f, c2 = 0.f, c3 = 0.f;
#pragma unroll
            for (int kc = 0; kc < 4; ++kc)
                asm("mma.sync.aligned.m16n8k16.row.col.f32.bf16.bf16.f32 "
                    "{%0,%1,%2,%3}, {%4,%5,%6,%7}, {%8,%9}, {%0,%1,%2,%3};"
                    : "+f"(c0), "+f"(c1), "+f"(c2), "+f"(c3)
                    : "r"(a[kc][0]), "r"(a[kc][1]), "r"(a[kc][2]), "r"(a[kc][3]),
                      "r"(b[kc].x), "r"(b[kc].y));

            if (it < 16) {
                mxA = fmaxf(mxA, fmaxf(c0, c1));
                mxB = fmaxf(mxB, fmaxf(c2, c3));
            } else {
                if (c0 >= thrA || c1 >= thrA || c2 >= thrB || c3 >= thrB) {
                    const int codeB = (ch * CHUNK_NT + ntl) * 8 + 2 * i4;
                    const int pA = pxw + g, pB = pA + 8;
                    if (c0 >= thrA) { int p = atomicAdd(s_nc, 1); if (p < CAND_CAP) s_cand[p] = (pA << 11) | codeB; }
                    if (c1 >= thrA) { int p = atomicAdd(s_nc, 1); if (p < CAND_CAP) s_cand[p] = (pA << 11) | (codeB + 1); }
                    if (c2 >= thrB) { int p = atomicAdd(s_nc, 1); if (p < CAND_CAP) s_cand[p] = (pB << 11) | codeB; }
                    if (c3 >= thrB) { int p = atomicAdd(s_nc, 1); if (p < CAND_CAP) s_cand[p] = (pB << 11) | (codeB + 1); }
                }
            }
        }

        __syncthreads();
        if (it < 30) {
            const int nc = (it + 2) & 15;
#pragma unroll
            for (int ii = 0; ii < 4; ++ii) {
                int o = (ii * 256 + tid) * 16;
                asm volatile("cp.async.cg.shared.global [%0], [%1], 16;"
                    :: "r"(smem_u + (it & 1) * 16384 + o),
                       "l"((const char*)g_cbf + nc * 16384 + o));
            }
            asm volatile("cp.async.commit_group;");
        }
    }

    // flush candidate list
    __syncthreads();
    int n = *s_nc; if (n > CAND_CAP) n = CAND_CAP;
    if (tid == 0) *s_base = atomicAdd(&g_ncand, n);
    __syncthreads();
    const int base = *s_base;
    for (int ii = tid; ii < n; ii += 256)
        if (base + ii < CAPG) g_cand[base + ii] = s_cand[ii];
    (void)out; (void)out_size;
}

// ---------------------------------------------------------------------------
// Kernel 5: exact fp32 rescore of candidates; winner via monotone-key atomicMax
// (exact value compare, lowest index on ties — order-independent).
// ---------------------------------------------------------------------------
__global__ void __launch_bounds__(256)
vq_rescore(const float* __restrict__ cb) {
    int n = g_ncand; if (n > CAPG) n = CAPG;
    for (int idx = blockIdx.x * 256 + threadIdx.x; idx < n; idx += gridDim.x * 256) {
        const int e = g_cand[idx];
        const int px = e >> 11, code = e & 2047;
        const float4* zr = (const float4*)(g_zt + (size_t)px * CDIM);
        const float4* er = (const float4*)(cb + (size_t)code * CDIM);
        float s = 0.f;
#pragma unroll
        for (int k = 0; k < 16; ++k) {
            float4 zv = zr[k], ev = er[k];
            s += zv.x * ev.x; s += zv.y * ev.y; s += zv.z * ev.z; s += zv.w * ev.w;
        }
        unsigned u = __float_as_uint(s);
        unsigned enc = (u & 0x80000000u) ? ~u : (u | 0x80000000u);
        unsigned long long key =
            ((unsigned long long)enc << 11) | (unsigned long long)(2047 - code);
        atomicMax(&g_key[px], key);
    }
}

// ---------------------------------------------------------------------------
// Kernel 6: z_q gather + straight-through out + MSE partials + histogram + idx.
// ---------------------------------------------------------------------------
__global__ void __launch_bounds__(256)
vq_out(const float* __restrict__ z, const float* __restrict__ cb,
       float* __restrict__ out, int out_size) {
    const int t = blockIdx.x * 256 + threadIdx.x;   // float4 index
    const int e = t * 4;
    const int c  = (e >> 12) & 63;
    const int b  = e >> 18;
    const int hw = e & 4095;
    const int p  = (b << 12) + hw;

    const float4 zv = *(const float4*)(z + e);
    const int i0 = 2047 - (int)(g_key[p]     & 2047ull);
    const int i1 = 2047 - (int)(g_key[p + 1] & 2047ull);
    const int i2 = 2047 - (int)(g_key[p + 2] & 2047ull);
    const int i3 = 2047 - (int)(g_key[p + 3] & 2047ull);

    const float q0 = cb[i0 * CDIM + c];
    const float q1 = cb[i1 * CDIM + c];
    const float q2 = cb[i2 * CDIM + c];
    const float q3 = cb[i3 * CDIM + c];

    float4 ov;
    ov.x = zv.x + (q0 - zv.x);
    ov.y = zv.y + (q1 - zv.y);
    ov.z = zv.z + (q2 - zv.z);
    ov.w = zv.w + (q3 - zv.w);
    *(float4*)(out + e) = ov;

    if (c == 0) {
        const int o = OFF_IDX + p;
        if (o + 3 < out_size) {
            out[o]     = (float)i0;
            out[o + 1] = (float)i1;
            out[o + 2] = (float)i2;
            out[o + 3] = (float)i3;
        }
        atomicAdd(&g_counts[i0], 1);
        atomicAdd(&g_counts[i1], 1);
        atomicAdd(&g_counts[i2], 1);
        atomicAdd(&g_counts[i3], 1);
    }

    const float d0 = q0 - zv.x, d1 = q1 - zv.y, d2 = q2 - zv.z, d3 = q3 - zv.w;
    float s = d0 * d0 + d1 * d1 + d2 * d2 + d3 * d3;

    __shared__ float red[256];
    red[threadIdx.x] = s;
    __syncthreads();
#pragma unroll
    for (int off = 128; off; off >>= 1) {
        if (threadIdx.x < off) red[threadIdx.x] += red[threadIdx.x + off];
        __syncthreads();
    }
    if (threadIdx.x == 0) g_partials[blockIdx.x] = red[0];
}

// ---------------------------------------------------------------------------
// Kernel 7: deterministic finalize — loss and perplexity.
// ---------------------------------------------------------------------------
__global__ void vq_fin(float* __restrict__ out, int out_size) {
    __shared__ float red[1024];
    const int t = threadIdx.x;

    float s = 0.0f;
#pragma unroll
    for (int i = 0; i < OUTBLOCKS / 1024; ++i) s += g_partials[i * 1024 + t];
    red[t] = s;
    __syncthreads();
#pragma unroll
    for (int off = 512; off; off >>= 1) {
        if (t < off) red[t] += red[t + off];
        __syncthreads();
    }
    if (t == 0 && OFF_LOSS < out_size)
        out[OFF_LOSS] = 1.25f * red[0] * (1.0f / (float)NELEM);
    __syncthreads();

    float h = 0.0f;
#pragma unroll
    for (int i = 0; i < NE / 1024; ++i) {
        float em = (float)g_counts[i * 1024 + t] * (1.0f / (float)NPIX);
        h += em * logf(em + 1e-10f);
    }
    red[t] = h;
    __syncthreads();
#pragma unroll
    for (int off = 512; off; off >>= 1) {
        if (t < off) red[t] += red[t + off];
        __syncthreads();
    }
    if (t == 0 && OFF_PERP < out_size)
        out[OFF_PERP] = expf(-red[0]);
}

// ---------------------------------------------------------------------------
extern "C" void kernel_launch(void* const* d_in, const int* in_sizes, int n_in,
                              void* d_out, int out_size) {
    const float* z  = (const float*)d_in[0];
    const float* cb = (const float*)d_in[1];
    float* out = (float*)d_out;

    const int mma_smem = 32768 + 1024 + CAND_CAP * 4 + 256;   // ~50.4 KB
    cudaFuncSetAttribute(vq_mma, cudaFuncAttributeMaxDynamicSharedMemorySize,
                         mma_smem);

    vq_prep_z<<<1024, 256>>>(z);
    vq_prep_cb<<<128, 256>>>(cb);
    vq_cbnorm<<<8, 256>>>(cb);
    vq_mma<<<GRID_MMA, 256, mma_smem>>>(out, out_size);
    vq_rescore<<<256, 256>>>(cb);
    vq_out<<<OUTBLOCKS, 256>>>(z, cb, out, out_size);
    vq_fin<<<1, 1024>>>(out, out_size);
}

// round 14
// speedup vs baseline: 3.2316x; 1.1001x over previous
#include <cuda_runtime.h>
#include <cuda_bf16.h>
#include <math.h>
#include <stdint.h>

// Problem constants
#define CDIM    64
#define NE      2048
#define HW      4096
#define NPIX    65536            // 16 * 4096
#define NELEM   4194304          // NPIX * CDIM

// Output layout: z_q [NELEM], loss, perplexity, indices [NPIX]
#define OFF_LOSS  NELEM
#define OFF_PERP  (NELEM + 1)
#define OFF_IDX   (NELEM + 2)

#define OUTBLOCKS 4096

// MMA tiling: block = 8 warps x 16 px = 128 px; codes in chunks of 128
#define BPX       128
#define GRID_MMA  (NPIX / BPX)        // 512
#define CHUNK_NT  16                  // n-tiles (8 codes) per chunk = 128 codes
#define NCHUNK    16
#define CAND_CAP  4096

// thr = runmax - COEF * ||z_p|| * Emax, COEF = 2*gamma = 2^-5 (gamma = 2^-6)
#define COEF_2G   0.03125f

// smem layout (bytes)
#define SMO_CB    0                   // 2 x 16KB code-frag chunks
#define SMO_CAND  32768               // uint[4096]
#define SMO_KEYS  49152               // ull[128]
#define SMO_THRQ  50176               // int[128]
#define SMO_NC    50688
#define SM_TOTAL  50720

// device state
__device__ uint2 g_cbf[(NE / 8) * 4 * 32];       // fragment-ready bf16 codebook
__device__ __nv_bfloat16 g_zh[NELEM];            // z bf16, [px][k]
__device__ float g_zt[NELEM];                    // z fp32, [px][k] (exact rescore)
__device__ float g_zn[NPIX];                     // ||z_p||
__device__ int   g_idx[NPIX];
__device__ int   g_emax_bits;                    // max ||e_c||^2 (float bits)
__device__ int   g_counts[NE];
__device__ float g_partials[OUTBLOCKS];

// ---------------------------------------------------------------------------
// Kernel 1: prep z — transpose to [px][k]; write fp32 + bf16 + norms.
// Block 0 zeroes per-replay state.
// ---------------------------------------------------------------------------
__global__ void __launch_bounds__(256)
vq_prep_z(const float* __restrict__ z) {
    __shared__ float ts[64 * 65];
    __shared__ float sn[256];
    const int tid = threadIdx.x;
    const int b   = blockIdx.x >> 6;
    const int hwt = blockIdx.x & 63;

    if (blockIdx.x == 0) {
#pragma unroll
        for (int i = 0; i < NE / 256; ++i) g_counts[i * 256 + tid] = 0;
        if (tid == 0) g_emax_bits = 0;
    }

    const float* src = z + (size_t)b * CDIM * HW + hwt * 64;
#pragma unroll
    for (int i = 0; i < 16; ++i) {
        int idx = i * 256 + tid;
        int c = idx >> 6, p = idx & 63;
        ts[c * 65 + p] = src[(size_t)c * HW + p];
    }
    __syncthreads();

    const int pl = tid >> 2, q = tid & 3;
    const int px = blockIdx.x * 64 + pl;
    float v[16];
    float nrm = 0.f;
#pragma unroll
    for (int cc = 0; cc < 16; ++cc) {
        float x = ts[(q * 16 + cc) * 65 + pl];
        v[cc] = x; nrm += x * x;
    }
    float4* zt4 = (float4*)(g_zt + (size_t)px * 64 + q * 16);
    zt4[0] = make_float4(v[0], v[1], v[2], v[3]);
    zt4[1] = make_float4(v[4], v[5], v[6], v[7]);
    zt4[2] = make_float4(v[8], v[9], v[10], v[11]);
    zt4[3] = make_float4(v[12], v[13], v[14], v[15]);

    unsigned hw_[8];
#pragma unroll
    for (int wdx = 0; wdx < 8; ++wdx) {
        __nv_bfloat162 h2 = __floats2bfloat162_rn(v[2 * wdx], v[2 * wdx + 1]);
        hw_[wdx] = *(unsigned*)&h2;
    }
    uint4* zh4 = (uint4*)((unsigned*)g_zh + (size_t)px * 32 + q * 8);
    zh4[0] = make_uint4(hw_[0], hw_[1], hw_[2], hw_[3]);
    zh4[1] = make_uint4(hw_[4], hw_[5], hw_[6], hw_[7]);

    sn[tid] = nrm;
    __syncthreads();
    if (tid < 64)
        g_zn[blockIdx.x * 64 + tid] =
            sqrtf(sn[tid * 4] + sn[tid * 4 + 1] + sn[tid * 4 + 2] + sn[tid * 4 + 3]);
}

// ---------------------------------------------------------------------------
// Kernel 2: prep codebook (frag layout) + per-code norms -> Emax.
// One thread per code.
// ---------------------------------------------------------------------------
__global__ void __launch_bounds__(256)
vq_prep_cb(const float* __restrict__ cb) {
    const int code = blockIdx.x * 256 + threadIdx.x;     // grid 8 -> 2048
    const float* r = cb + (size_t)code * CDIM;
    float v[64];
    float s = 0.f;
#pragma unroll
    for (int k = 0; k < 64; ++k) { v[k] = r[k]; s += v[k] * v[k]; }
    atomicMax(&g_emax_bits, __float_as_int(s));

    const int nt = code >> 3, lq = code & 7;
#pragma unroll
    for (int kc = 0; kc < 4; ++kc) {
#pragma unroll
        for (int j = 0; j < 4; ++j) {
            int w1 = kc * 8 + j, w2 = w1 + 4;
            __nv_bfloat162 b0 = __floats2bfloat162_rn(v[2 * w1], v[2 * w1 + 1]);
            __nv_bfloat162 b1 = __floats2bfloat162_rn(v[2 * w2], v[2 * w2 + 1]);
            g_cbf[nt * 128 + kc * 32 + lq * 4 + j] =
                make_uint2(*(unsigned*)&b0, *(unsigned*)&b1);
        }
    }
}

// ---------------------------------------------------------------------------
// Kernel 3: single-sweep bf16 HMMA GEMM with running threshold + fused
// exact rescore + in-block winner resolution.
// Candidate word (unsigned!): [31:25]=pxl, [24:14]=code, [13:0]=quantized approx.
// ---------------------------------------------------------------------------
__global__ void __launch_bounds__(256, 4)
vq_mma(const float* __restrict__ cb, float* __restrict__ out, int out_size) {
    extern __shared__ char smem[];
    uint2* s_cb = (uint2*)(smem + SMO_CB);
    unsigned* s_cand = (unsigned*)(smem + SMO_CAND);
    unsigned long long* s_keys = (unsigned long long*)(smem + SMO_KEYS);
    int*   s_thrq = (int*)(smem + SMO_THRQ);
    int*   s_nc   = (int*)(smem + SMO_NC);

    const int tid  = threadIdx.x;
    const int lane = tid & 31;
    const int w    = tid >> 5;
    const int g    = lane >> 2;
    const int i4   = lane & 3;
    const int px0  = blockIdx.x * BPX;
    const int pxw  = px0 + w * 16;
    const int rowA = w * 16 + g;          // local px rows
    const int rowB = rowA + 8;

    unsigned smem_u;
    asm("{ .reg .u64 t; cvta.to.shared.u64 t, %1; cvt.u32.u64 %0, t; }"
        : "=r"(smem_u) : "l"(smem));

    if (tid == 0) *s_nc = 0;
    if (tid < 128) s_keys[tid] = 0ull;

    // A fragments resident in regs (4 k-chunks x 4 b32)
    unsigned a[4][4];
    {
        const unsigned* zw = (const unsigned*)g_zh;
        const size_t rA = (size_t)(pxw + g) * 32;
        const size_t rB = (size_t)(pxw + g + 8) * 32;
#pragma unroll
        for (int kc = 0; kc < 4; ++kc) {
            a[kc][0] = zw[rA + kc * 8 + i4];
            a[kc][1] = zw[rB + kc * 8 + i4];
            a[kc][2] = zw[rA + kc * 8 + i4 + 4];
            a[kc][3] = zw[rB + kc * 8 + i4 + 4];
        }
    }

    const float coef = COEF_2G * sqrtf(__int_as_float(g_emax_bits));
    const float offA = coef * g_zn[pxw + g];
    const float offB = coef * g_zn[pxw + g + 8];

    // prefetch chunks 0,1
#pragma unroll
    for (int pc = 0; pc < 2; ++pc) {
#pragma unroll
        for (int ii = 0; ii < 4; ++ii) {
            int o = (ii * 256 + tid) * 16;
            asm volatile("cp.async.cg.shared.global [%0], [%1], 16;"
                :: "r"(smem_u + pc * 16384 + o),
                   "l"((const char*)g_cbf + pc * 16384 + o));
        }
        asm volatile("cp.async.commit_group;");
    }

    float runA = -3.402823e38f, runB = -3.402823e38f;

    for (int it = 0; it < NCHUNK; ++it) {
        if (it == NCHUNK - 1) asm volatile("cp.async.wait_group 0;");
        else                  asm volatile("cp.async.wait_group 1;");
        __syncthreads();

        const uint2* cbb = s_cb + (it & 1) * 2048;
#pragma unroll 4
        for (int ntl = 0; ntl < CHUNK_NT; ++ntl) {
            uint2 b[4];
#pragma unroll
            for (int kc = 0; kc < 4; ++kc)
                b[kc] = cbb[ntl * 128 + kc * 32 + lane];

            float c0 = 0.f, c1 = 0.f, c2 = 0.f, c3 = 0.f;
            float d0 = 0.f, d1 = 0.f, d2 = 0.f, d3 = 0.f;
#pragma unroll
            for (int kc = 0; kc < 4; kc += 2) {
                asm("mma.sync.aligned.m16n8k16.row.col.f32.bf16.bf16.f32 "
                    "{%0,%1,%2,%3}, {%4,%5,%6,%7}, {%8,%9}, {%0,%1,%2,%3};"
                    : "+f"(c0), "+f"(c1), "+f"(c2), "+f"(c3)
                    : "r"(a[kc][0]), "r"(a[kc][1]), "r"(a[kc][2]), "r"(a[kc][3]),
                      "r"(b[kc].x), "r"(b[kc].y));
                asm("mma.sync.aligned.m16n8k16.row.col.f32.bf16.bf16.f32 "
                    "{%0,%1,%2,%3}, {%4,%5,%6,%7}, {%8,%9}, {%0,%1,%2,%3};"
                    : "+f"(d0), "+f"(d1), "+f"(d2), "+f"(d3)
                    : "r"(a[kc + 1][0]), "r"(a[kc + 1][1]), "r"(a[kc + 1][2]), "r"(a[kc + 1][3]),
                      "r"(b[kc + 1].x), "r"(b[kc + 1].y));
            }
            c0 += d0; c1 += d1; c2 += d2; c3 += d3;

            // running max (quad-synced) and emission
            float mA = fmaxf(c0, c1), mB = fmaxf(c2, c3);
            mA = fmaxf(mA, __shfl_xor_sync(0xFFFFFFFFu, mA, 1));
            mA = fmaxf(mA, __shfl_xor_sync(0xFFFFFFFFu, mA, 2));
            mB = fmaxf(mB, __shfl_xor_sync(0xFFFFFFFFu, mB, 1));
            mB = fmaxf(mB, __shfl_xor_sync(0xFFFFFFFFu, mB, 2));
            runA = fmaxf(runA, mA);
            runB = fmaxf(runB, mB);
            const float tA = runA - offA, tB = runB - offB;

            if (c0 >= tA || c1 >= tA || c2 >= tB || c3 >= tB) {
                const int code0 = (it * CHUNK_NT + ntl) * 8 + 2 * i4;
#pragma unroll
                for (int s = 0; s < 4; ++s) {
                    const float cv = (s == 0) ? c0 : (s == 1) ? c1 : (s == 2) ? c2 : c3;
                    const float tv = (s < 2) ? tA : tB;
                    if (cv >= tv) {
                        int qv = (int)((cv + 64.f) * 128.f);
                        qv = max(0, min(16383, qv));
                        const unsigned pxl = (s < 2) ? (unsigned)rowA : (unsigned)rowB;
                        const unsigned cd  = (unsigned)(code0 + (s & 1));
                        int p = atomicAdd(s_nc, 1);
                        if (p < CAND_CAP)
                            s_cand[p] = (pxl << 25) | (cd << 14) | (unsigned)qv;
                    }
                }
            }
        }

        __syncthreads();
        if (it + 2 < NCHUNK) {
#pragma unroll
            for (int ii = 0; ii < 4; ++ii) {
                int o = (ii * 256 + tid) * 16;
                asm volatile("cp.async.cg.shared.global [%0], [%1], 16;"
                    :: "r"(smem_u + (it & 1) * 16384 + o),
                       "l"((const char*)g_cbf + (it + 2) * 16384 + o));
            }
            asm volatile("cp.async.commit_group;");
        }
    }

    // final per-pixel quantized thresholds
    if (i4 == 0) {
        int qa = (int)((runA - offA + 64.f) * 128.f);
        int qb = (int)((runB - offB + 64.f) * 128.f);
        s_thrq[rowA] = max(0, min(16383, qa));
        s_thrq[rowB] = max(0, min(16383, qb));
    }
    __syncthreads();

    // filter + exact fp32 rescore + in-block winner resolution
    int n = *s_nc; if (n > CAND_CAP) n = CAND_CAP;
    for (int ii = tid; ii < n; ii += 256) {
        const unsigned wv  = s_cand[ii];
        const int pxl = (int)(wv >> 25);               // unsigned decode!
        const int cd  = (int)((wv >> 14) & 2047u);
        const int qv  = (int)(wv & 16383u);
        if (qv + 2 < s_thrq[pxl]) continue;
        const float4* zr = (const float4*)(g_zt + (size_t)(px0 + pxl) * CDIM);
        const float4* er = (const float4*)(cb + (size_t)cd * CDIM);
        float s = 0.f;
#pragma unroll
        for (int k = 0; k < 16; ++k) {
            float4 zv = zr[k], ev = er[k];
            s += zv.x * ev.x; s += zv.y * ev.y; s += zv.z * ev.z; s += zv.w * ev.w;
        }
        unsigned u = __float_as_uint(s);
        unsigned enc = (u & 0x80000000u) ? ~u : (u | 0x80000000u);
        unsigned long long key =
            ((unsigned long long)enc << 11) | (unsigned long long)(2047 - cd);
        atomicMax(&s_keys[pxl], key);
    }
    __syncthreads();

    if (tid < 128) {
        const int idx = 2047 - (int)(s_keys[tid] & 2047ull);
        g_idx[px0 + tid] = idx;
        const int o = OFF_IDX + px0 + tid;
        if (o < out_size) out[o] = (float)idx;
    }
}

// ---------------------------------------------------------------------------
// Kernel 4: z_q gather + straight-through out + MSE partials + histogram.
// ---------------------------------------------------------------------------
__global__ void __launch_bounds__(256)
vq_out(const float* __restrict__ z, const float* __restrict__ cb,
       float* __restrict__ out) {
    const int t = blockIdx.x * 256 + threadIdx.x;   // float4 index
    const int e = t * 4;
    const int c  = (e >> 12) & 63;
    const int b  = e >> 18;
    const int hw = e & 4095;
    const int p  = (b << 12) + hw;

    const float4 zv = *(const float4*)(z + e);
    const int4  iv  = *(const int4*)(g_idx + p);

    const float q0 = cb[iv.x * CDIM + c];
    const float q1 = cb[iv.y * CDIM + c];
    const float q2 = cb[iv.z * CDIM + c];
    const float q3 = cb[iv.w * CDIM + c];

    float4 ov;
    ov.x = zv.x + (q0 - zv.x);
    ov.y = zv.y + (q1 - zv.y);
    ov.z = zv.z + (q2 - zv.z);
    ov.w = zv.w + (q3 - zv.w);
    *(float4*)(out + e) = ov;

    if (c == 0) {
        atomicAdd(&g_counts[iv.x], 1);
        atomicAdd(&g_counts[iv.y], 1);
        atomicAdd(&g_counts[iv.z], 1);
        atomicAdd(&g_counts[iv.w], 1);
    }

    const float d0 = q0 - zv.x, d1 = q1 - zv.y, d2 = q2 - zv.z, d3 = q3 - zv.w;
    float s = d0 * d0 + d1 * d1 + d2 * d2 + d3 * d3;

    __shared__ float red[256];
    red[threadIdx.x] = s;
    __syncthreads();
#pragma unroll
    for (int off = 128; off; off >>= 1) {
        if (threadIdx.x < off) red[threadIdx.x] += red[threadIdx.x + off];
        __syncthreads();
    }
    if (threadIdx.x == 0) g_partials[blockIdx.x] = red[0];
}

// ---------------------------------------------------------------------------
// Kernel 5: deterministic finalize — loss and perplexity.
// ---------------------------------------------------------------------------
__global__ void vq_fin(float* __restrict__ out, int out_size) {
    __shared__ float red[1024];
    const int t = threadIdx.x;

    float s = 0.0f;
#pragma unroll
    for (int i = 0; i < OUTBLOCKS / 1024; ++i) s += g_partials[i * 1024 + t];
    red[t] = s;
    __syncthreads();
#pragma unroll
    for (int off = 512; off; off >>= 1) {
        if (t < off) red[t] += red[t + off];
        __syncthreads();
    }
    if (t == 0 && OFF_LOSS < out_size)
        out[OFF_LOSS] = 1.25f * red[0] * (1.0f / (float)NELEM);
    __syncthreads();

    float h = 0.0f;
#pragma unroll
    for (int i = 0; i < NE / 1024; ++i) {
        float em = (float)g_counts[i * 1024 + t] * (1.0f / (float)NPIX);
        h += em * logf(em + 1e-10f);
    }
    red[t] = h;
    __syncthreads();
#pragma unroll
    for (int off = 512; off; off >>= 1) {
        if (t < off) red[t] += red[t + off];
        __syncthreads();
    }
    if (t == 0 && OFF_PERP < out_size)
        out[OFF_PERP] = expf(-red[0]);
}

// ---------------------------------------------------------------------------
extern "C" void kernel_launch(void* const* d_in, const int* in_sizes, int n_in,
                              void* d_out, int out_size) {
    const float* z  = (const float*)d_in[0];
    const float* cb = (const float*)d_in[1];
    float* out = (float*)d_out;

    cudaFuncSetAttribute(vq_mma, cudaFuncAttributeMaxDynamicSharedMemorySize,
                         SM_TOTAL);

    vq_prep_z<<<1024, 256>>>(z);
    vq_prep_cb<<<8, 256>>>(cb);
    vq_mma<<<GRID_MMA, 256, SM_TOTAL>>>(cb, out, out_size);
    vq_out<<<OUTBLOCKS, 256>>>(z, cb, out);
    vq_fin<<<1, 1024>>>(out, out_size);
}